// round 1
// baseline (speedup 1.0000x reference)
#include <cuda_runtime.h>

// Problem constants (fixed by the dataset shapes)
#define HB_ 32
#define WB_ 32
#define CC_ 64
#define HA_ 512
#define WA_ 512
#define NN_ 256
#define BB_ 4
#define PATCH_ (HB_ * WB_)   // 1024
#define PLANE_ (HA_ * WA_)   // 262144

__global__ __launch_bounds__(1024, 1)
void aerial_patch_sampler_kernel(const float* __restrict__ img,
                                 const float* __restrict__ pose,
                                 float* __restrict__ out)
{
    const int bn = blockIdx.x;        // b * N + n
    const int b  = bn >> 8;           // N = 256
    const int wb = threadIdx.x & 31;
    const int hb = threadIdx.x >> 5;

    // Pose for this patch (same for all 1024 threads; broadcast via L1/L2)
    const float u  = __ldg(&pose[bn * 3 + 0]);
    const float v  = __ldg(&pose[bn * 3 + 1]);
    const float th = __ldg(&pose[bn * 3 + 2]);

    // cos_r = cos(-th) = cos(th); sin_r = sin(-th) = -sin(th)
    const float c = cosf(th);
    const float s = sinf(th);

    const float gu0 = (float)(HB_ - 1 - hb);      // rows flipped
    const float gv0 = (float)(wb - WB_ / 2);      // centered on WB/2

    // gu = u + cos_r*gu0 - sin_r*gv0 = u + c*gu0 + s*gv0
    // gv = v + sin_r*gu0 + cos_r*gv0 = v - s*gu0 + c*gv0
    const float gu = u + c * gu0 + s * gv0;
    const float gv = v - s * gu0 + c * gv0;

    // Normalize exactly like the reference (FEATURE_SCALE = 1)
    const float inv_w = 2.0f / (float)WA_;
    const float inv_h = 2.0f / (float)HA_;
    const float gx = (gu + 0.5f) * inv_w - 1.0f;
    const float gy = (gv + 0.5f) * inv_h - 1.0f;
    const bool valid = (fabsf(gx) < 1.0f) && (fabsf(gy) < 1.0f);

    // Output: out[((bn)*C + c)*1024 + hb*32 + wb]
    float* op = out + (size_t)bn * CC_ * PATCH_ + threadIdx.x;

    if (!valid) {
        #pragma unroll
        for (int cc = 0; cc < CC_; cc++)
            op[cc * PATCH_] = 0.0f;
        return;
    }

    // Unnormalize (align_corners=False), same round-trip as reference
    const float ix = ((gx + 1.0f) * (float)WA_ - 1.0f) * 0.5f;
    const float iy = ((gy + 1.0f) * (float)HA_ - 1.0f) * 0.5f;

    const float x0f = floorf(ix);
    const float y0f = floorf(iy);
    const int x0 = (int)x0f;
    const int y0 = (int)y0f;
    const int x1 = x0 + 1;
    const int y1 = y0 + 1;

    const float wx1 = ix - x0f;
    const float wx0 = 1.0f - wx1;
    const float wy1 = iy - y0f;
    const float wy0 = 1.0f - wy1;

    const bool vx0 = (x0 >= 0) && (x0 < WA_);
    const bool vx1 = (x1 >= 0) && (x1 < WA_);
    const bool vy0 = (y0 >= 0) && (y0 < HA_);
    const bool vy1 = (y1 >= 0) && (y1 < HA_);

    const float w00 = (vx0 && vy0) ? (wx0 * wy0) : 0.0f;
    const float w10 = (vx1 && vy0) ? (wx1 * wy0) : 0.0f;
    const float w01 = (vx0 && vy1) ? (wx0 * wy1) : 0.0f;
    const float w11 = (vx1 && vy1) ? (wx1 * wy1) : 0.0f;

    const int xc0 = min(max(x0, 0), WA_ - 1);
    const int xc1 = min(max(x1, 0), WA_ - 1);
    const int yc0 = min(max(y0, 0), HA_ - 1);
    const int yc1 = min(max(y1, 0), HA_ - 1);

    const int i00 = yc0 * WA_ + xc0;
    const int i10 = yc0 * WA_ + xc1;
    const int i01 = yc1 * WA_ + xc0;
    const int i11 = yc1 * WA_ + xc1;

    const float* base = img + (size_t)b * CC_ * PLANE_;

    #pragma unroll 8
    for (int cc = 0; cc < CC_; cc++) {
        const float* p = base + cc * PLANE_;
        const float f00 = __ldg(p + i00);
        const float f10 = __ldg(p + i10);
        const float f01 = __ldg(p + i01);
        const float f11 = __ldg(p + i11);
        op[cc * PATCH_] = w00 * f00 + w10 * f10 + w01 * f01 + w11 * f11;
    }
}

extern "C" void kernel_launch(void* const* d_in, const int* in_sizes, int n_in,
                              void* d_out, int out_size)
{
    const float* aer_feat = (const float*)d_in[0];   // (B, C, 512, 512) fp32
    const float* pose_uvr = (const float*)d_in[1];   // (B, N, 3) fp32
    float* out = (float*)d_out;                      // (B, N, C, 32, 32) fp32

    dim3 grid(BB_ * NN_);   // 1024 blocks, b-major for L2 batch locality
    dim3 block(1024);       // one thread per patch pixel
    aerial_patch_sampler_kernel<<<grid, block>>>(aer_feat, pose_uvr, out);
}

// round 2
// speedup vs baseline: 1.3505x; 1.3505x over previous
#include <cuda_runtime.h>

// Problem constants (fixed by the dataset shapes)
#define HB_ 32
#define WB_ 32
#define CC_ 64
#define HA_ 512
#define WA_ 512
#define NN_ 256
#define BB_ 4
#define PATCH_ (HB_ * WB_)   // 1024
#define PLANE_ (HA_ * WA_)   // 262144
#define CHUNK_ 4             // channels per load batch (16 loads in flight)

__global__ __launch_bounds__(256, 5)
void aerial_patch_sampler_kernel(const float* __restrict__ img,
                                 const float* __restrict__ pose,
                                 float* __restrict__ out)
{
    const int bn = blockIdx.x;        // b * N + n  (b-major: L2 batch locality)
    const int b  = bn >> 8;           // N = 256

    // Warp-tile remap: each warp covers an 8(wb) x 4(hb) patch tile so its
    // rotated image footprint spans ~8-10 rows instead of ~20-32.
    const int lane = threadIdx.x & 31;
    const int warp = threadIdx.x >> 5;            // 0..7
    const int wb = (lane & 7) + ((warp & 3) << 3);                 // 0..31
    const int hb = (blockIdx.y << 3) + (lane >> 3) + ((warp >> 2) << 2); // 0..31

    // Pose for this patch (broadcast)
    const float u  = __ldg(&pose[bn * 3 + 0]);
    const float v  = __ldg(&pose[bn * 3 + 1]);
    const float th = __ldg(&pose[bn * 3 + 2]);

    // cos_r = cos(-th) = cos(th); sin_r = sin(-th) = -sin(th)
    const float c = cosf(th);
    const float s = sinf(th);

    const float gu0 = (float)(HB_ - 1 - hb);      // rows flipped
    const float gv0 = (float)(wb - WB_ / 2);      // centered on WB/2

    const float gu = u + c * gu0 + s * gv0;
    const float gv = v - s * gu0 + c * gv0;

    // Normalize exactly like the reference (FEATURE_SCALE = 1)
    const float gx = (gu + 0.5f) * (2.0f / (float)WA_) - 1.0f;
    const float gy = (gv + 0.5f) * (2.0f / (float)HA_) - 1.0f;
    const bool valid = (fabsf(gx) < 1.0f) && (fabsf(gy) < 1.0f);

    // Output: out[((bn)*C + cc)*1024 + hb*32 + wb]
    float* op = out + (size_t)bn * CC_ * PATCH_ + hb * WB_ + wb;

    if (!valid) {
        #pragma unroll
        for (int cc = 0; cc < CC_; cc++)
            op[cc * PATCH_] = 0.0f;
        return;
    }

    // Unnormalize (align_corners=False), same round-trip as reference
    const float ix = ((gx + 1.0f) * (float)WA_ - 1.0f) * 0.5f;
    const float iy = ((gy + 1.0f) * (float)HA_ - 1.0f) * 0.5f;

    const float x0f = floorf(ix);
    const float y0f = floorf(iy);
    const int x0 = (int)x0f;
    const int y0 = (int)y0f;
    const int x1 = x0 + 1;
    const int y1 = y0 + 1;

    const float wx1 = ix - x0f;
    const float wx0 = 1.0f - wx1;
    const float wy1 = iy - y0f;
    const float wy0 = 1.0f - wy1;

    const bool vx0 = (x0 >= 0) && (x0 < WA_);
    const bool vx1 = (x1 >= 0) && (x1 < WA_);
    const bool vy0 = (y0 >= 0) && (y0 < HA_);
    const bool vy1 = (y1 >= 0) && (y1 < HA_);

    const float w00 = (vx0 && vy0) ? (wx0 * wy0) : 0.0f;
    const float w10 = (vx1 && vy0) ? (wx1 * wy0) : 0.0f;
    const float w01 = (vx0 && vy1) ? (wx0 * wy1) : 0.0f;
    const float w11 = (vx1 && vy1) ? (wx1 * wy1) : 0.0f;

    const int xc0 = min(max(x0, 0), WA_ - 1);
    const int xc1 = min(max(x1, 0), WA_ - 1);
    const int yc0 = min(max(y0, 0), HA_ - 1);
    const int yc1 = min(max(y1, 0), HA_ - 1);

    const float* base = img + (size_t)b * CC_ * PLANE_;
    const float* p00 = base + yc0 * WA_ + xc0;
    const float* p10 = base + yc0 * WA_ + xc1;
    const float* p01 = base + yc1 * WA_ + xc0;
    const float* p11 = base + yc1 * WA_ + xc1;

    // 4-channel chunks: 16 independent loads in flight before any consumer.
    #pragma unroll 1
    for (int cc0 = 0; cc0 < CC_; cc0 += CHUNK_) {
        float f00[CHUNK_], f10[CHUNK_], f01[CHUNK_], f11[CHUNK_];
        #pragma unroll
        for (int j = 0; j < CHUNK_; j++) {
            const int off = (cc0 + j) * PLANE_;
            f00[j] = __ldg(p00 + off);
            f10[j] = __ldg(p10 + off);
            f01[j] = __ldg(p01 + off);
            f11[j] = __ldg(p11 + off);
        }
        #pragma unroll
        for (int j = 0; j < CHUNK_; j++) {
            op[(cc0 + j) * PATCH_] =
                w00 * f00[j] + w10 * f10[j] + w01 * f01[j] + w11 * f11[j];
        }
    }
}

extern "C" void kernel_launch(void* const* d_in, const int* in_sizes, int n_in,
                              void* d_out, int out_size)
{
    const float* aer_feat = (const float*)d_in[0];   // (B, C, 512, 512) fp32
    const float* pose_uvr = (const float*)d_in[1];   // (B, N, 3) fp32
    float* out = (float*)d_out;                      // (B, N, C, 32, 32) fp32

    dim3 grid(BB_ * NN_, HB_ / 8);  // x: patch (b-major), y: 8-row band of patch
    dim3 block(256);                // 8 warps, each an 8x4 pixel tile
    aerial_patch_sampler_kernel<<<grid, block>>>(aer_feat, pose_uvr, out);
}